// round 15
// baseline (speedup 1.0000x reference)
#include <cuda_runtime.h>
#include <cuda_fp16.h>
#include <cstdint>
#include <math.h>

#define N_NODES 8192
#define F_DIM   256
#define ALPHA   0.2f
#define M_CTA   64
#define KT      128
#define NTILES  (N_NODES / KT)     // 64

// ---------------- scratch (device globals; no allocation allowed) ------------
__device__ float  g_Wh[N_NODES * F_DIM];      // 8 MB fp32
__device__ __half g_Wh_h[N_NODES * F_DIM];    // 4 MB fp16
__device__ float  g_S1[N_NODES];
__device__ float  g_S2[N_NODES];
__device__ float  g_E2[N_NODES];
__device__ float  g_F2[N_NODES];

// ---------------- helpers ----------------------------------------------------
__device__ __forceinline__ uint32_t smem_u32(const void* p) {
    uint32_t a;
    asm("{ .reg .u64 t; cvta.to.shared.u64 t, %1; cvt.u32.u64 %0, t; }"
        : "=r"(a) : "l"(p));
    return a;
}
__device__ __forceinline__ void ldsm_x4(uint32_t* r, uint32_t addr) {
    asm volatile("ldmatrix.sync.aligned.m8n8.x4.shared.b16 {%0,%1,%2,%3}, [%4];"
                 : "=r"(r[0]), "=r"(r[1]), "=r"(r[2]), "=r"(r[3]) : "r"(addr));
}
__device__ __forceinline__ void ldsm_x4_t(uint32_t* r, uint32_t addr) {
    asm volatile("ldmatrix.sync.aligned.m8n8.x4.trans.shared.b16 {%0,%1,%2,%3}, [%4];"
                 : "=r"(r[0]), "=r"(r[1]), "=r"(r[2]), "=r"(r[3]) : "r"(addr));
}
__device__ __forceinline__ void mma_f16(float* c, const uint32_t* a, const uint32_t* b) {
    asm volatile(
        "mma.sync.aligned.m16n8k16.row.col.f32.f16.f16.f32 "
        "{%0,%1,%2,%3}, {%4,%5,%6,%7}, {%8,%9}, {%0,%1,%2,%3};"
        : "+f"(c[0]), "+f"(c[1]), "+f"(c[2]), "+f"(c[3])
        : "r"(a[0]), "r"(a[1]), "r"(a[2]), "r"(a[3]), "r"(b[0]), "r"(b[1]));
}
__device__ __forceinline__ void cp16(uint32_t dst, const void* src) {
    asm volatile("cp.async.cg.shared.global [%0], [%1], 16;"
                 :: "r"(dst), "l"(src) : "memory");
}
#define CP_COMMIT() asm volatile("cp.async.commit_group;" ::: "memory")
#define CP_WAIT0()  asm volatile("cp.async.wait_group 0;" ::: "memory")

// ============================================================================
// Kernel 1: Wh = h @ W + b (fp32 FFMA, R12-proven) + fused fp16 emit
// ============================================================================
__global__ __launch_bounds__(256) void k_wh_gemm(const float* __restrict__ h,
                                                 const float* __restrict__ W,
                                                 const float* __restrict__ b) {
    __shared__ float As[16][68];
    __shared__ float Bs[16][64];
    const int tid = threadIdx.x;
    const int i0 = blockIdx.x * 64, j0 = blockIdx.y * 64;
    const int tn = tid % 16, tm = tid / 16;
    float acc[4][4];
#pragma unroll
    for (int r = 0; r < 4; r++)
#pragma unroll
        for (int c = 0; c < 4; c++) acc[r][c] = 0.f;
    const int arow = tid / 4, akg = tid % 4, bk = tid / 16, bcg = tid % 16;
    for (int k0 = 0; k0 < F_DIM; k0 += 16) {
        float4 av = *(const float4*)&h[(size_t)(i0 + arow) * F_DIM + k0 + akg * 4];
        float4 bv = *(const float4*)&W[(size_t)(k0 + bk) * F_DIM + j0 + bcg * 4];
        __syncthreads();
        As[akg * 4 + 0][arow] = av.x; As[akg * 4 + 1][arow] = av.y;
        As[akg * 4 + 2][arow] = av.z; As[akg * 4 + 3][arow] = av.w;
        *(float4*)&Bs[bk][bcg * 4] = bv;
        __syncthreads();
#pragma unroll
        for (int kk = 0; kk < 16; kk++) {
            float4 a4 = *(const float4*)&As[kk][tm * 4];
            float4 b4 = *(const float4*)&Bs[kk][tn * 4];
            const float ar[4] = {a4.x, a4.y, a4.z, a4.w};
            const float br[4] = {b4.x, b4.y, b4.z, b4.w};
#pragma unroll
            for (int r = 0; r < 4; r++)
#pragma unroll
                for (int c = 0; c < 4; c++) acc[r][c] += ar[r] * br[c];
        }
    }
    float4 bias = *(const float4*)&b[j0 + tn * 4];
#pragma unroll
    for (int r = 0; r < 4; r++) {
        float4 o;
        o.x = acc[r][0] + bias.x; o.y = acc[r][1] + bias.y;
        o.z = acc[r][2] + bias.z; o.w = acc[r][3] + bias.w;
        const size_t off = (size_t)(i0 + tm * 4 + r) * F_DIM + j0 + tn * 4;
        *(float4*)&g_Wh[off] = o;
        __half2 p0 = __floats2half2_rn(o.x, o.y);
        __half2 p1 = __floats2half2_rn(o.z, o.w);
        *(uint2*)&g_Wh_h[off] = make_uint2(*(uint32_t*)&p0, *(uint32_t*)&p1);
    }
}

// ============================================================================
// Kernel 2: per-node scores + exp tables
// ============================================================================
__global__ __launch_bounds__(256) void k_scores(const float* __restrict__ a) {
    const int row  = blockIdx.x * 8 + (threadIdx.x >> 5);
    const int lane = threadIdx.x & 31;
    float acc1 = 0.f, acc2 = 0.f;
#pragma unroll
    for (int t = 0; t < 8; t++) {
        const int k = lane + t * 32;
        const float w = g_Wh[(size_t)row * F_DIM + k];
        acc1 += w * a[k];
        acc2 += w * a[F_DIM + k];
    }
#pragma unroll
    for (int off = 16; off > 0; off >>= 1) {
        acc1 += __shfl_xor_sync(0xffffffffu, acc1, off);
        acc2 += __shfl_xor_sync(0xffffffffu, acc2, off);
    }
    if (lane == 0) {
        g_S1[row] = acc1;
        g_S2[row] = acc2;
        g_E2[row] = expf(acc2);
        g_F2[row] = expf(ALPHA * acc2);
    }
}

// ============================================================================
// Kernel 3: fused masked-softmax AV GEMM, single-product fp16 HMMA
// CTA: 64 rows x 256 feats, 1024 thr (32 warps: 4M x 8N), warp tile 16x32
// KEY CHANGE vs R12: KT 64 -> 128 (NTILES 64) — halves per-tile overhead
// (barriers, phase ramps, buildA/stageB call cost). Double-buffered A and B;
// stageB(t+1) issued after barrier(t) => race-free (same invariant as R12).
// ============================================================================
#define A_PITCH 272
#define B_PITCH 528
#define ABUF(b)   ((b) * 17408)            // A[64][128] f16, pitch 272 (x2)
#define BBUF(b)   (34816 + (b) * 67584)    // B[128][256] f16, pitch 528 (x2)
#define SMEM_DYN  169984

__global__ __launch_bounds__(1024, 1) void k_attn_av(const int* __restrict__ adj,
                                                     float* __restrict__ out) {
    extern __shared__ __align__(16) char dyn[];
    __shared__ float sDsum[M_CTA][16];
    __shared__ float sInv[M_CTA];

    const int tid = threadIdx.x;
    const int wid = tid >> 5, lane = tid & 31;
    const int i0 = blockIdx.x * M_CTA;
    const uint32_t sBase = smem_u32(dyn);

    // roles
    const int bm = tid >> 4;            // weight-build row 0..63
    const int bj = (tid & 15) * 8;      // j-chunk (8 j's within KT=128)
    const int cj = tid >> 3;            // cp.async j row 0..127
    const int cc = (tid & 7) * 64;      // cp.async byte offset in 512B row
    const int m0w = (wid & 3) * 16;     // warp M origin (4 M-warps x 16)
    const int n0w = (wid >> 2) * 32;    // warp N origin (8 N-warps x 32)

    const float s1 = g_S1[i0 + bm];
    const float e1 = expf(s1), f1 = expf(ALPHA * s1), t1 = -s1;
    float ds = 0.f;

    float acc[4][4];                    // [nf][4]
#pragma unroll
    for (int nf = 0; nf < 4; nf++)
#pragma unroll
        for (int c = 0; c < 4; c++) acc[nf][c] = 0.f;

    // ---- B tile stage via cp.async (64 B per thread) into buf t&1 ----
    auto stageB = [&](int t) {
        const size_t gb = ((size_t)(t * KT + cj) * F_DIM) * 2 + cc;
        const uint32_t sm = sBase + BBUF(t & 1) + cj * B_PITCH + cc;
#pragma unroll
        for (int q = 0; q < 4; q++)
            cp16(sm + 16 * q, (const char*)g_Wh_h + gb + 16 * q);
        CP_COMMIT();
    };
    // ---- A build: 8 weights/thread; denominator from DEQUANTIZED fp16 vals ----
    auto buildA = [&](int buf, const int4* adjv, const float4* s2v,
                      const float4* e2v, const float4* f2v) {
        const int   ai[8]  = {adjv[0].x, adjv[0].y, adjv[0].z, adjv[0].w,
                              adjv[1].x, adjv[1].y, adjv[1].z, adjv[1].w};
        const float s2a[8] = {s2v[0].x, s2v[0].y, s2v[0].z, s2v[0].w,
                              s2v[1].x, s2v[1].y, s2v[1].z, s2v[1].w};
        const float e2a[8] = {e2v[0].x, e2v[0].y, e2v[0].z, e2v[0].w,
                              e2v[1].x, e2v[1].y, e2v[1].z, e2v[1].w};
        const float f2a[8] = {f2v[0].x, f2v[0].y, f2v[0].z, f2v[0].w,
                              f2v[1].x, f2v[1].y, f2v[1].z, f2v[1].w};
        float wv[8];
#pragma unroll
        for (int c = 0; c < 8; c++) {
            float w = 0.f;
            if (ai[c] > 0) w = (s2a[c] > t1) ? e1 * e2a[c] : f1 * f2a[c];
            wv[c] = w;
        }
        uint32_t p[4];
#pragma unroll
        for (int q = 0; q < 4; q++) {
            __half2 hq = __floats2half2_rn(wv[2 * q], wv[2 * q + 1]);
            p[q] = *(uint32_t*)&hq;
            const float2 dq = __half22float2(hq);
            ds += dq.x + dq.y;                 // denominator == quantized numerator
        }
        *(uint4*)(dyn + ABUF(buf) + bm * A_PITCH + bj * 2) =
            make_uint4(p[0], p[1], p[2], p[3]);
    };

    const int lr = lane & 15;
    const int lc = lane >> 4;

    // ---- prologue: stage tile 0; build A(0) ----
    {
        stageB(0);
        int4 adjv[2]; float4 s2v[2], e2v[2], f2v[2];
        const size_t ab = (size_t)(i0 + bm) * N_NODES + bj;
        adjv[0] = *(const int4*)&adj[ab];
        adjv[1] = *(const int4*)&adj[ab + 4];
        s2v[0] = *(const float4*)&g_S2[bj]; s2v[1] = *(const float4*)&g_S2[bj + 4];
        e2v[0] = *(const float4*)&g_E2[bj]; e2v[1] = *(const float4*)&g_E2[bj + 4];
        f2v[0] = *(const float4*)&g_F2[bj]; f2v[1] = *(const float4*)&g_F2[bj + 4];
        buildA(0, adjv, s2v, e2v, f2v);
    }

    int4 adjv[2]; float4 s2v[2], e2v[2], f2v[2];
    for (int t = 0; t < NTILES; t++) {
        const bool more = (t + 1 < NTILES);

        // gmem loads for buildA(t+1) — registers only
        if (more) {
            const int jn = (t + 1) * KT;
            const size_t ab = (size_t)(i0 + bm) * N_NODES + jn + bj;
            adjv[0] = *(const int4*)&adj[ab];
            adjv[1] = *(const int4*)&adj[ab + 4];
            s2v[0] = *(const float4*)&g_S2[jn + bj]; s2v[1] = *(const float4*)&g_S2[jn + bj + 4];
            e2v[0] = *(const float4*)&g_E2[jn + bj]; e2v[1] = *(const float4*)&g_E2[jn + bj + 4];
            f2v[0] = *(const float4*)&g_F2[jn + bj]; f2v[1] = *(const float4*)&g_F2[jn + bj + 4];
        }

        CP_WAIT0();        // B(t) landed (issued one full tile ago)
        __syncthreads();   // A(t), B(t) visible; all warps finished MMA(t-1)

        // stage B(t+1) into buf cur^1 — its last readers (MMA(t-1)) are done
        if (more) stageB(t + 1);

        const uint32_t aBase = sBase + ABUF(t & 1);
        const uint32_t bBase = sBase + BBUF(t & 1);
#pragma unroll
        for (int kk = 0; kk < 8; kk++) {
            const int k16 = (kk + wid) & 7;    // stagger crossbar bursts by warp
            const int k0 = k16 * 16;
            uint32_t ah[4], bb[2][4];
            ldsm_x4(ah, aBase + (m0w + lr) * A_PITCH + (k0 + 8 * lc) * 2);
#pragma unroll
            for (int nh = 0; nh < 2; nh++)
                ldsm_x4_t(bb[nh], bBase + (k0 + lr) * B_PITCH + (n0w + nh * 16 + 8 * lc) * 2);
#pragma unroll
            for (int nf = 0; nf < 4; nf++)
                mma_f16(acc[nf], ah, &bb[nf >> 1][(nf & 1) * 2]);
        }

        if (more) buildA((t + 1) & 1, adjv, s2v, e2v, f2v);
    }

    // ---- denominator reduce ----
    __syncthreads();
    sDsum[bm][tid & 15] = ds;
    __syncthreads();
    if (tid < M_CTA) {
        float s = 0.f;
#pragma unroll
        for (int g = 0; g < 16; g++) s += sDsum[tid][g];
        sInv[tid] = 1.0f / s;
    }
    __syncthreads();

    // ---- epilogue: normalize + store ----
    {
        const int r0 = m0w + (lane >> 2);
        const float inv0 = sInv[r0];
        const float inv1 = sInv[r0 + 8];
#pragma unroll
        for (int nf = 0; nf < 4; nf++) {
            const int col = n0w + nf * 8 + (lane & 3) * 2;
            float2 v0 = {acc[nf][0] * inv0, acc[nf][1] * inv0};
            float2 v1 = {acc[nf][2] * inv1, acc[nf][3] * inv1};
            *(float2*)&out[(size_t)(i0 + r0) * F_DIM + col] = v0;
            *(float2*)&out[(size_t)(i0 + r0 + 8) * F_DIM + col] = v1;
        }
    }
}

// ============================================================================
extern "C" void kernel_launch(void* const* d_in, const int* in_sizes, int n_in,
                              void* d_out, int out_size) {
    const float* h   = (const float*)d_in[0];
    const int*   adj = (const int*)d_in[1];
    const float* Ww  = (const float*)d_in[2];
    const float* Wb  = (const float*)d_in[3];
    const float* a   = (const float*)d_in[4];
    float* out = (float*)d_out;

    static int attr_done = 0;
    if (!attr_done) {
        cudaFuncSetAttribute(k_attn_av, cudaFuncAttributeMaxDynamicSharedMemorySize,
                             SMEM_DYN);
        attr_done = 1;
    }

    k_wh_gemm<<<dim3(N_NODES / 64, F_DIM / 64), 256>>>(h, Ww, Wb);
    k_scores<<<N_NODES / 8, 256>>>(a);
    k_attn_av<<<N_NODES / M_CTA, 1024, SMEM_DYN>>>(adj, out);
}

// round 16
// speedup vs baseline: 1.5308x; 1.5308x over previous
#include <cuda_runtime.h>
#include <cuda_fp16.h>
#include <cstdint>
#include <math.h>

#define N_NODES 8192
#define F_DIM   256
#define ALPHA   0.2f
#define M_CTA   64
#define KT      64
#define NTILES  (N_NODES / KT)     // 128

// ---------------- scratch (device globals; no allocation allowed) ------------
__device__ float  g_Wh[N_NODES * F_DIM];      // 8 MB fp32
__device__ __half g_Wh_h[N_NODES * F_DIM];    // 4 MB fp16
__device__ float  g_S1[N_NODES];
__device__ float  g_S2[N_NODES];
__device__ float  g_E2[N_NODES];
__device__ float  g_F2[N_NODES];

// ---------------- helpers ----------------------------------------------------
__device__ __forceinline__ uint32_t smem_u32(const void* p) {
    uint32_t a;
    asm("{ .reg .u64 t; cvta.to.shared.u64 t, %1; cvt.u32.u64 %0, t; }"
        : "=r"(a) : "l"(p));
    return a;
}
__device__ __forceinline__ void ldsm_x4(uint32_t* r, uint32_t addr) {
    asm volatile("ldmatrix.sync.aligned.m8n8.x4.shared.b16 {%0,%1,%2,%3}, [%4];"
                 : "=r"(r[0]), "=r"(r[1]), "=r"(r[2]), "=r"(r[3]) : "r"(addr));
}
__device__ __forceinline__ void ldsm_x4_t(uint32_t* r, uint32_t addr) {
    asm volatile("ldmatrix.sync.aligned.m8n8.x4.trans.shared.b16 {%0,%1,%2,%3}, [%4];"
                 : "=r"(r[0]), "=r"(r[1]), "=r"(r[2]), "=r"(r[3]) : "r"(addr));
}
__device__ __forceinline__ void mma_f16(float* c, const uint32_t* a, const uint32_t* b) {
    asm volatile(
        "mma.sync.aligned.m16n8k16.row.col.f32.f16.f16.f32 "
        "{%0,%1,%2,%3}, {%4,%5,%6,%7}, {%8,%9}, {%0,%1,%2,%3};"
        : "+f"(c[0]), "+f"(c[1]), "+f"(c[2]), "+f"(c[3])
        : "r"(a[0]), "r"(a[1]), "r"(a[2]), "r"(a[3]), "r"(b[0]), "r"(b[1]));
}
__device__ __forceinline__ void cp16(uint32_t dst, const void* src) {
    asm volatile("cp.async.cg.shared.global [%0], [%1], 16;"
                 :: "r"(dst), "l"(src) : "memory");
}
#define CP_COMMIT() asm volatile("cp.async.commit_group;" ::: "memory")
#define CP_WAIT0()  asm volatile("cp.async.wait_group 0;" ::: "memory")
#define CP_WAIT1()  asm volatile("cp.async.wait_group 1;" ::: "memory")

// ============================================================================
// Kernel 1: Wh = h @ W + b (fp32 FFMA) + fused fp16 emit   [R12-identical]
// ============================================================================
__global__ __launch_bounds__(256) void k_wh_gemm(const float* __restrict__ h,
                                                 const float* __restrict__ W,
                                                 const float* __restrict__ b) {
    __shared__ float As[16][68];
    __shared__ float Bs[16][64];
    const int tid = threadIdx.x;
    const int i0 = blockIdx.x * 64, j0 = blockIdx.y * 64;
    const int tn = tid % 16, tm = tid / 16;
    float acc[4][4];
#pragma unroll
    for (int r = 0; r < 4; r++)
#pragma unroll
        for (int c = 0; c < 4; c++) acc[r][c] = 0.f;
    const int arow = tid / 4, akg = tid % 4, bk = tid / 16, bcg = tid % 16;
    for (int k0 = 0; k0 < F_DIM; k0 += 16) {
        float4 av = *(const float4*)&h[(size_t)(i0 + arow) * F_DIM + k0 + akg * 4];
        float4 bv = *(const float4*)&W[(size_t)(k0 + bk) * F_DIM + j0 + bcg * 4];
        __syncthreads();
        As[akg * 4 + 0][arow] = av.x; As[akg * 4 + 1][arow] = av.y;
        As[akg * 4 + 2][arow] = av.z; As[akg * 4 + 3][arow] = av.w;
        *(float4*)&Bs[bk][bcg * 4] = bv;
        __syncthreads();
#pragma unroll
        for (int kk = 0; kk < 16; kk++) {
            float4 a4 = *(const float4*)&As[kk][tm * 4];
            float4 b4 = *(const float4*)&Bs[kk][tn * 4];
            const float ar[4] = {a4.x, a4.y, a4.z, a4.w};
            const float br[4] = {b4.x, b4.y, b4.z, b4.w};
#pragma unroll
            for (int r = 0; r < 4; r++)
#pragma unroll
                for (int c = 0; c < 4; c++) acc[r][c] += ar[r] * br[c];
        }
    }
    float4 bias = *(const float4*)&b[j0 + tn * 4];
#pragma unroll
    for (int r = 0; r < 4; r++) {
        float4 o;
        o.x = acc[r][0] + bias.x; o.y = acc[r][1] + bias.y;
        o.z = acc[r][2] + bias.z; o.w = acc[r][3] + bias.w;
        const size_t off = (size_t)(i0 + tm * 4 + r) * F_DIM + j0 + tn * 4;
        *(float4*)&g_Wh[off] = o;
        __half2 p0 = __floats2half2_rn(o.x, o.y);
        __half2 p1 = __floats2half2_rn(o.z, o.w);
        *(uint2*)&g_Wh_h[off] = make_uint2(*(uint32_t*)&p0, *(uint32_t*)&p1);
    }
}

// ============================================================================
// Kernel 2: per-node scores + exp tables   [R12-identical]
// ============================================================================
__global__ __launch_bounds__(256) void k_scores(const float* __restrict__ a) {
    const int row  = blockIdx.x * 8 + (threadIdx.x >> 5);
    const int lane = threadIdx.x & 31;
    float acc1 = 0.f, acc2 = 0.f;
#pragma unroll
    for (int t = 0; t < 8; t++) {
        const int k = lane + t * 32;
        const float w = g_Wh[(size_t)row * F_DIM + k];
        acc1 += w * a[k];
        acc2 += w * a[F_DIM + k];
    }
#pragma unroll
    for (int off = 16; off > 0; off >>= 1) {
        acc1 += __shfl_xor_sync(0xffffffffu, acc1, off);
        acc2 += __shfl_xor_sync(0xffffffffu, acc2, off);
    }
    if (lane == 0) {
        g_S1[row] = acc1;
        g_S2[row] = acc2;
        g_E2[row] = expf(acc2);
        g_F2[row] = expf(ALPHA * acc2);
    }
}

// ============================================================================
// Kernel 3: fused masked-softmax AV GEMM, single-product fp16 HMMA
// CTA: 64 rows x 256 feats, 1024 thr (32 warps: 4M x 8N), warp tile 16x32
// Triple-buffered B (cp.async, distance 2), one barrier/tile.
// CHANGE vs R12 (only): buildA(t+1) hoisted BEFORE the MMA loop (right after
// barrier(t)) — same safety argument as stageB(t+2): buffer (t+1)&1's last
// readers are MMA(t-1), and barrier(t) orders all of them before this write.
// The build's ALU work now fills the warps' initial ldsm-latency shadow.
// ============================================================================
#define A_PITCH 144
#define B_PITCH 528
#define ABUF(b)   ((b) * 9216)             // A[64][64] f16, pitch 144 (x2)
#define BBUF(b)   (18432 + (b) * 33792)    // B[64][256] f16, pitch 528 (x3)
#define SMEM_DYN  119808

__global__ __launch_bounds__(1024, 1) void k_attn_av(const int* __restrict__ adj,
                                                     float* __restrict__ out) {
    extern __shared__ __align__(16) char dyn[];
    __shared__ float sDsum[M_CTA][16];
    __shared__ float sInv[M_CTA];

    const int tid = threadIdx.x;
    const int wid = tid >> 5, lane = tid & 31;
    const int i0 = blockIdx.x * M_CTA;
    const uint32_t sBase = smem_u32(dyn);

    // roles
    const int bm = tid >> 4;            // weight-build row 0..63
    const int bj = (tid & 15) * 4;      // j-chunk (4 j's within KT=64)
    const int cj = tid >> 4;            // cp.async j row 0..63
    const int cc = (tid & 15) * 32;     // cp.async byte offset in 512B row
    const int m0w = (wid & 3) * 16;     // warp M origin (4 M-warps x 16)
    const int n0w = (wid >> 2) * 32;    // warp N origin (8 N-warps x 32)

    const float s1 = g_S1[i0 + bm];
    const float e1 = expf(s1), f1 = expf(ALPHA * s1), t1 = -s1;
    float ds = 0.f;

    float acc[4][4];                    // [nf][4]
#pragma unroll
    for (int nf = 0; nf < 4; nf++)
#pragma unroll
        for (int c = 0; c < 4; c++) acc[nf][c] = 0.f;

    auto stageB = [&](int t) {
        const size_t gb = ((size_t)(t * KT + cj) * F_DIM) * 2 + cc;
        const uint32_t sm = sBase + BBUF(t % 3) + cj * B_PITCH + cc;
        cp16(sm,      (const char*)g_Wh_h + gb);
        cp16(sm + 16, (const char*)g_Wh_h + gb + 16);
        CP_COMMIT();
    };
    auto buildA = [&](int buf, int4 adjv, float4 s2v, float4 e2v, float4 f2v) {
        const int   ai[4]  = {adjv.x, adjv.y, adjv.z, adjv.w};
        const float s2a[4] = {s2v.x, s2v.y, s2v.z, s2v.w};
        const float e2a[4] = {e2v.x, e2v.y, e2v.z, e2v.w};
        const float f2a[4] = {f2v.x, f2v.y, f2v.z, f2v.w};
        float wv[4];
#pragma unroll
        for (int c = 0; c < 4; c++) {
            float w = 0.f;
            if (ai[c] > 0) w = (s2a[c] > t1) ? e1 * e2a[c] : f1 * f2a[c];
            wv[c] = w;
        }
        uint32_t p[2];
#pragma unroll
        for (int q = 0; q < 2; q++) {
            __half2 hq = __floats2half2_rn(wv[2 * q], wv[2 * q + 1]);
            p[q] = *(uint32_t*)&hq;
            const float2 dq = __half22float2(hq);
            ds += dq.x + dq.y;                 // denominator == quantized numerator
        }
        *(uint2*)(dyn + ABUF(buf) + bm * A_PITCH + bj * 2) = make_uint2(p[0], p[1]);
    };

    const int lr = lane & 15;
    const int lc = lane >> 4;

    // ---- prologue: stage tiles 0,1; build A(0) ----
    {
        stageB(0);
        stageB(1);
        const size_t ab = (size_t)(i0 + bm) * N_NODES + bj;
        buildA(0, *(const int4*)&adj[ab],
               *(const float4*)&g_S2[bj], *(const float4*)&g_E2[bj],
               *(const float4*)&g_F2[bj]);
    }

    int4 adjv; float4 s2v, e2v, f2v;
    for (int t = 0; t < NTILES; t++) {
        const bool more = (t + 1 < NTILES);

        // gmem loads for buildA(t+1) — registers only, issued early
        if (more) {
            const int jn = (t + 1) * KT;
            adjv = *(const int4*)&adj[(size_t)(i0 + bm) * N_NODES + jn + bj];
            s2v = *(const float4*)&g_S2[jn + bj];
            e2v = *(const float4*)&g_E2[jn + bj];
            f2v = *(const float4*)&g_F2[jn + bj];
        }

        CP_WAIT1();
        __syncthreads();   // A(t), B(t) visible; all warps past MMA(t-1)

        // stage B(t+2) — its last readers (MMA(t-1)) are done
        if (t + 2 < NTILES) stageB(t + 2);
        else CP_COMMIT();   // keep group counting uniform

        // HOISTED: build A(t+1) into buffer (t+1)&1 — last readers were
        // MMA(t-1), ordered before us by barrier(t). ALU work lands in the
        // ldsm-latency shadow of the MMA phase below.
        if (more) buildA((t + 1) & 1, adjv, s2v, e2v, f2v);

        const uint32_t aBase = sBase + ABUF(t & 1);
        const uint32_t bBase = sBase + BBUF(t % 3);
#pragma unroll
        for (int kk = 0; kk < 4; kk++) {
            const int k16 = (kk + wid) & 3;    // stagger crossbar bursts by warp
            const int k0 = k16 * 16;
            uint32_t ah[4], bb[2][4];
            ldsm_x4(ah, aBase + (m0w + lr) * A_PITCH + (k0 + 8 * lc) * 2);
#pragma unroll
            for (int nh = 0; nh < 2; nh++)
                ldsm_x4_t(bb[nh], bBase + (k0 + lr) * B_PITCH + (n0w + nh * 16 + 8 * lc) * 2);
#pragma unroll
            for (int nf = 0; nf < 4; nf++)
                mma_f16(acc[nf], ah, &bb[nf >> 1][(nf & 1) * 2]);
        }
    }

    // ---- denominator reduce ----
    __syncthreads();
    sDsum[bm][tid & 15] = ds;
    __syncthreads();
    if (tid < M_CTA) {
        float s = 0.f;
#pragma unroll
        for (int g = 0; g < 16; g++) s += sDsum[tid][g];
        sInv[tid] = 1.0f / s;
    }
    __syncthreads();

    // ---- epilogue: normalize + store ----
    {
        const int r0 = m0w + (lane >> 2);
        const float inv0 = sInv[r0];
        const float inv1 = sInv[r0 + 8];
#pragma unroll
        for (int nf = 0; nf < 4; nf++) {
            const int col = n0w + nf * 8 + (lane & 3) * 2;
            float2 v0 = {acc[nf][0] * inv0, acc[nf][1] * inv0};
            float2 v1 = {acc[nf][2] * inv1, acc[nf][3] * inv1};
            *(float2*)&out[(size_t)(i0 + r0) * F_DIM + col] = v0;
            *(float2*)&out[(size_t)(i0 + r0 + 8) * F_DIM + col] = v1;
        }
    }
}

// ============================================================================
extern "C" void kernel_launch(void* const* d_in, const int* in_sizes, int n_in,
                              void* d_out, int out_size) {
    const float* h   = (const float*)d_in[0];
    const int*   adj = (const int*)d_in[1];
    const float* Ww  = (const float*)d_in[2];
    const float* Wb  = (const float*)d_in[3];
    const float* a   = (const float*)d_in[4];
    float* out = (float*)d_out;

    static int attr_done = 0;
    if (!attr_done) {
        cudaFuncSetAttribute(k_attn_av, cudaFuncAttributeMaxDynamicSharedMemorySize,
                             SMEM_DYN);
        attr_done = 1;
    }

    k_wh_gemm<<<dim3(N_NODES / 64, F_DIM / 64), 256>>>(h, Ww, Wb);
    k_scores<<<N_NODES / 8, 256>>>(a);
    k_attn_av<<<N_NODES / M_CTA, 1024, SMEM_DYN>>>(adj, out);
}